// round 13
// baseline (speedup 1.0000x reference)
#include <cuda_runtime.h>
#include <math_constants.h>
#include <cstdint>

// ---------------- problem constants ----------------
#define PB 8192
#define PK 8192
#define PD 512
#define LDZ 1024
#define LDSC 16384

// ---------------- tiling ----------------
#define BM 128
#define BN 128
#define BK 16
#define NK (PD / BK)     // 32
#define NSTG 4
#define NTILE (PK / BN)  // 64

#define ROWB 48
#define T_BYTES (128 * ROWB)
#define STG_BYTES (4 * T_BYTES)
#define SMEM_TOTAL (NSTG * STG_BYTES)  // 98304 (F path uses a 48KB subset)
#define OFF_AH 0
#define OFF_AL (T_BYTES)
#define OFF_BH (2 * T_BYTES)
#define OFF_BL (3 * T_BYTES)

// ---------------- device scratch ----------------
__device__ uint16_t g_Zh[(size_t)PB * LDZ];
__device__ uint16_t g_Zl[(size_t)PB * LDZ];
__device__ uint16_t g_Wh[(size_t)2 * PK * PD];
__device__ uint16_t g_Wl[(size_t)2 * PK * PD];
__device__ unsigned long long g_cand[(size_t)PB * 2 * NTILE];   // 8 MB

// ---------------- helpers ----------------
static __device__ __forceinline__ uint32_t pack_bf16(float lo, float hi) {
    uint32_t r;
    asm("cvt.rn.bf16x2.f32 %0, %1, %2;" : "=r"(r) : "f"(hi), "f"(lo));
    return r;
}
static __device__ __forceinline__ void mma16816(float* c, const uint32_t* a, const uint32_t* b) {
    asm volatile(
        "mma.sync.aligned.m16n8k16.row.col.f32.bf16.bf16.f32 "
        "{%0,%1,%2,%3}, {%4,%5,%6,%7}, {%8,%9}, {%0,%1,%2,%3};"
        : "+f"(c[0]), "+f"(c[1]), "+f"(c[2]), "+f"(c[3])
        : "r"(a[0]), "r"(a[1]), "r"(a[2]), "r"(a[3]), "r"(b[0]), "r"(b[1]));
}
static __device__ __forceinline__ uint32_t smem_u32(const void* p) {
    uint32_t a;
    asm("{ .reg .u64 t; cvta.to.shared.u64 t, %1; cvt.u32.u64 %0, t; }" : "=r"(a) : "l"(p));
    return a;
}
static __device__ __forceinline__ uint64_t glob_u64(const void* p) {
    uint64_t a;
    asm("cvta.to.global.u64 %0, %1;" : "=l"(a) : "l"(p));
    return a;
}
#define CP16(dst, src) \
    asm volatile("cp.async.cg.shared.global [%0], [%1], 16;" :: "r"(dst), "l"(src))
#define CP_COMMIT() asm volatile("cp.async.commit_group;" ::: "memory")
#define CP_WAIT1()  asm volatile("cp.async.wait_group 1;" ::: "memory")
#define CP_WAIT2()  asm volatile("cp.async.wait_group 2;" ::: "memory")

static __device__ __forceinline__ unsigned long long score_key(float v, int col) {
    uint32_t u = __float_as_uint(v);
    u = (u & 0x80000000u) ? ~u : (u | 0x80000000u);
    return ((unsigned long long)u << 32) | (uint32_t)(~col);
}
static __device__ __forceinline__ unsigned long long kmax(unsigned long long a,
                                                          unsigned long long b) {
    return a > b ? a : b;
}

struct Frags {
    uint32_t ah[4][4], al[4][4], bh[4][2], bl[4][2];
};

// ---------------------------------------------------------------------------
// Kernel 0: split f32 -> bf16 hi + bf16 lo residual.
// ---------------------------------------------------------------------------
__global__ __launch_bounds__(256)
void split_kernel(const float* __restrict__ Z,
                  const float* __restrict__ Wa,
                  const float* __restrict__ Wv)
{
    const int region = blockIdx.y;
    const size_t i = ((size_t)blockIdx.x * 256 + threadIdx.x);
    const size_t nquads = (region == 0) ? ((size_t)PB * LDZ / 4) : ((size_t)PK * PD / 4);
    if (i >= nquads) return;

    const float* src;
    uint16_t *dh, *dl;
    if (region == 0)      { src = Z;  dh = g_Zh; dl = g_Zl; }
    else if (region == 1) { src = Wa; dh = g_Wh; dl = g_Wl; }
    else                  { src = Wv; dh = g_Wh + (size_t)PK * PD; dl = g_Wl + (size_t)PK * PD; }

    float4 v = *(const float4*)(src + 4 * i);
    uint32_t h0 = pack_bf16(v.x, v.y);
    uint32_t h1 = pack_bf16(v.z, v.w);
    float r0 = v.x - __uint_as_float(h0 << 16);
    float r1 = v.y - __uint_as_float(h0 & 0xFFFF0000u);
    float r2 = v.z - __uint_as_float(h1 << 16);
    float r3 = v.w - __uint_as_float(h1 & 0xFFFF0000u);
    ((uint2*)dh)[i] = make_uint2(h0, h1);
    ((uint2*)dl)[i] = make_uint2(pack_bf16(r0, r1), pack_bf16(r2, r3));
}

// ---------------------------------------------------------------------------
// Tensor path (class T): R12 mainloop, fused argmax epilogue.
// ---------------------------------------------------------------------------
static __device__ __forceinline__ void tensor_path(char* sm, float* __restrict__ scores,
                                                   int xtile, int bm, int g, int tid)
{
    const uint32_t sb = smem_u32(sm);
    const int lane = tid & 31;
    const int w    = tid >> 5;
    const int wm   = w >> 2;
    const int wn   = w & 3;
    const int bn   = xtile * BN;

    const int lr = tid >> 1;
    const int kh = tid & 1;
    const uint64_t srcAH = glob_u64(g_Zh + (size_t)(bm + lr) * LDZ + g * PD + kh * 8);
    const uint64_t srcAL = glob_u64(g_Zl + (size_t)(bm + lr) * LDZ + g * PD + kh * 8);
    const uint64_t srcBH = glob_u64(g_Wh + ((size_t)g * PK + bn + lr) * PD + kh * 8);
    const uint64_t srcBL = glob_u64(g_Wl + ((size_t)g * PK + bn + lr) * PD + kh * 8);
    const uint32_t doff = (uint32_t)(lr * ROWB + kh * 16);

    const int qr = lane >> 2;
    const int qi = lane & 3;
    const int qc = qi * 4;
    const int a_base = (wm * 64 + qr) * ROWB + qc;
    const int b_base = (wn * 32 + qr) * ROWB + qc;

    float acc[4][4][4];
#pragma unroll
    for (int i = 0; i < 4; i++)
#pragma unroll
        for (int j = 0; j < 4; j++)
#pragma unroll
            for (int q = 0; q < 4; q++) acc[i][j][q] = 0.f;

#define ISSUE(slot, kt_) do {                                            \
    const uint32_t st_ = sb + (slot) * STG_BYTES + doff;                 \
    const uint64_t kb_ = (uint64_t)(kt_) * 32;                           \
    CP16(st_ + OFF_AH, srcAH + kb_);                                     \
    CP16(st_ + OFF_AL, srcAL + kb_);                                     \
    CP16(st_ + OFF_BH, srcBH + kb_);                                     \
    CP16(st_ + OFF_BL, srcBL + kb_);                                     \
} while (0)

#define LOAD_FRAGS(F, stg) do {                                                   \
    _Pragma("unroll")                                                             \
    for (int mt = 0; mt < 4; mt++) {                                              \
        const int m0 = a_base + mt * 16 * ROWB;                                   \
        const int m8 = m0 + 8 * ROWB;                                             \
        (F).ah[mt][0] = *(const uint32_t*)((stg) + OFF_AH + m0);                  \
        (F).ah[mt][1] = *(const uint32_t*)((stg) + OFF_AH + m8);                  \
        (F).ah[mt][2] = *(const uint32_t*)((stg) + OFF_AH + m0 + 16);             \
        (F).ah[mt][3] = *(const uint32_t*)((stg) + OFF_AH + m8 + 16);             \
        (F).al[mt][0] = *(const uint32_t*)((stg) + OFF_AL + m0);                  \
        (F).al[mt][1] = *(const uint32_t*)((stg) + OFF_AL + m8);                  \
        (F).al[mt][2] = *(const uint32_t*)((stg) + OFF_AL + m0 + 16);             \
        (F).al[mt][3] = *(const uint32_t*)((stg) + OFF_AL + m8 + 16);             \
    }                                                                             \
    _Pragma("unroll")                                                             \
    for (int nt = 0; nt < 4; nt++) {                                              \
        const int n0 = b_base + nt * 8 * ROWB;                                    \
        (F).bh[nt][0] = *(const uint32_t*)((stg) + OFF_BH + n0);                  \
        (F).bh[nt][1] = *(const uint32_t*)((stg) + OFF_BH + n0 + 16);             \
        (F).bl[nt][0] = *(const uint32_t*)((stg) + OFF_BL + n0);                  \
        (F).bl[nt][1] = *(const uint32_t*)((stg) + OFF_BL + n0 + 16);             \
    }                                                                             \
} while (0)

#define MMA_ALL(F) do {                                                           \
    _Pragma("unroll")                                                             \
    for (int nt = 0; nt < 4; nt++)                                                \
        _Pragma("unroll")                                                         \
        for (int mt = 0; mt < 4; mt++) mma16816(acc[mt][nt], (F).ah[mt], (F).bh[nt]); \
    _Pragma("unroll")                                                             \
    for (int nt = 0; nt < 4; nt++)                                                \
        _Pragma("unroll")                                                         \
        for (int mt = 0; mt < 4; mt++) mma16816(acc[mt][nt], (F).al[mt], (F).bh[nt]); \
    _Pragma("unroll")                                                             \
    for (int nt = 0; nt < 4; nt++)                                                \
        _Pragma("unroll")                                                         \
        for (int mt = 0; mt < 4; mt++) mma16816(acc[mt][nt], (F).ah[mt], (F).bl[nt]); \
} while (0)

    ISSUE(0, 0); CP_COMMIT();
    ISSUE(1, 1); CP_COMMIT();
    ISSUE(2, 2); CP_COMMIT();

    Frags F0, F1;
    CP_WAIT2();
    __syncthreads();
    LOAD_FRAGS(F0, sm);

#pragma unroll 2
    for (int kt = 0; kt < NK; kt++) {
        CP_WAIT1();
        __syncthreads();

        if (kt + 3 < NK) ISSUE((kt + 3) & 3, kt + 3);
        CP_COMMIT();

        if (kt & 1) {
            if (kt + 1 < NK) LOAD_FRAGS(F0, sm + ((kt + 1) & 3) * STG_BYTES);
            MMA_ALL(F1);
        } else {
            if (kt + 1 < NK) LOAD_FRAGS(F1, sm + ((kt + 1) & 3) * STG_BYTES);
            MMA_ALL(F0);
        }
    }
#undef ISSUE
#undef LOAD_FRAGS
#undef MMA_ALL

    __syncthreads();
    unsigned long long* red = (unsigned long long*)sm;

    const size_t gcol = (size_t)g * PK + bn;
#pragma unroll
    for (int mt = 0; mt < 4; mt++) {
        const int rl0 = wm * 64 + mt * 16 + qr;
        const int r0  = bm + rl0;
        unsigned long long k0 = 0, k1 = 0;
#pragma unroll
        for (int nt = 0; nt < 4; nt++) {
            const int c0 = wn * 32 + nt * 8 + qi * 2;
            float2 lo = make_float2(acc[mt][nt][0], acc[mt][nt][1]);
            float2 hi = make_float2(acc[mt][nt][2], acc[mt][nt][3]);
            *(float2*)(scores + (size_t)r0 * LDSC + gcol + c0)       = lo;
            *(float2*)(scores + (size_t)(r0 + 8) * LDSC + gcol + c0) = hi;
            const int gc = bn + c0;
            k0 = kmax(k0, kmax(score_key(lo.x, gc), score_key(lo.y, gc + 1)));
            k1 = kmax(k1, kmax(score_key(hi.x, gc), score_key(hi.y, gc + 1)));
        }
#pragma unroll
        for (int m = 1; m <= 2; m <<= 1) {
            k0 = kmax(k0, __shfl_xor_sync(0xFFFFFFFFu, k0, m));
            k1 = kmax(k1, __shfl_xor_sync(0xFFFFFFFFu, k1, m));
        }
        if (qi == 0) {
            red[(size_t)rl0 * 4 + wn]       = k0;
            red[(size_t)(rl0 + 8) * 4 + wn] = k1;
        }
    }
    __syncthreads();
    if (tid < 128) {
        unsigned long long k = kmax(kmax(red[tid * 4 + 0], red[tid * 4 + 1]),
                                    kmax(red[tid * 4 + 2], red[tid * 4 + 3]));
        g_cand[(((size_t)(bm + tid)) * 2 + g) * NTILE + xtile] = k;
    }
}

// ---------------------------------------------------------------------------
// FFMA path (class F): exact fp32 SGEMM (Round-4 proven), fused argmax epi.
// Uses the FMA pipe, which is idle in tensor-class CTAs.
// ---------------------------------------------------------------------------
static __device__ __forceinline__ void ffma_path(const float* __restrict__ Z,
                                                 const float* __restrict__ W,
                                                 char* sm, float* __restrict__ scores,
                                                 int xtile, int bm, int g, int tid)
{
    // smem layout (floats): As[2][16][128] at 0, Bs[2][16][128] at 4096
    float* As = (float*)sm;
    float* Bs = (float*)sm + 4096;

    const int ty = tid >> 4;
    const int tx = tid & 15;
    const int bn = xtile * BN;

    const float* A = Z + g * PD;

    const int lrow = tid >> 2;
    const int lk   = (tid & 3) * 4;
    const float* Ag = A + (size_t)(bm + lrow) * LDZ + lk;
    const float* Wg = W + (size_t)(bn + lrow) * PD  + lk;

    float acc[8][8];
#pragma unroll
    for (int i = 0; i < 8; i++)
#pragma unroll
        for (int j = 0; j < 8; j++) acc[i][j] = 0.f;

    float4 pa0, pa1, pb0, pb1;
    pa0 = *(const float4*)(Ag);
    pa1 = *(const float4*)(Ag + (size_t)64 * LDZ);
    pb0 = *(const float4*)(Wg);
    pb1 = *(const float4*)(Wg + (size_t)64 * PD);

#define STS_TILE(st) do {                                                              \
    As[(st)*2048 + (lk+0)*128 + lrow]    = pa0.x; As[(st)*2048 + (lk+1)*128 + lrow]    = pa0.y; \
    As[(st)*2048 + (lk+2)*128 + lrow]    = pa0.z; As[(st)*2048 + (lk+3)*128 + lrow]    = pa0.w; \
    As[(st)*2048 + (lk+0)*128 + lrow+64] = pa1.x; As[(st)*2048 + (lk+1)*128 + lrow+64] = pa1.y; \
    As[(st)*2048 + (lk+2)*128 + lrow+64] = pa1.z; As[(st)*2048 + (lk+3)*128 + lrow+64] = pa1.w; \
    Bs[(st)*2048 + (lk+0)*128 + lrow]    = pb0.x; Bs[(st)*2048 + (lk+1)*128 + lrow]    = pb0.y; \
    Bs[(st)*2048 + (lk+2)*128 + lrow]    = pb0.z; Bs[(st)*2048 + (lk+3)*128 + lrow]    = pb0.w; \
    Bs[(st)*2048 + (lk+0)*128 + lrow+64] = pb1.x; Bs[(st)*2048 + (lk+1)*128 + lrow+64] = pb1.y; \
    Bs[(st)*2048 + (lk+2)*128 + lrow+64] = pb1.z; Bs[(st)*2048 + (lk+3)*128 + lrow+64] = pb1.w; \
} while (0)

    STS_TILE(0);
    __syncthreads();

    int s = 0;
    for (int kt = 0; kt < NK; kt++) {
        if (kt + 1 < NK) {
            const float* Ag2 = Ag + (kt + 1) * BK;
            const float* Wg2 = Wg + (kt + 1) * BK;
            pa0 = *(const float4*)(Ag2);
            pa1 = *(const float4*)(Ag2 + (size_t)64 * LDZ);
            pb0 = *(const float4*)(Wg2);
            pb1 = *(const float4*)(Wg2 + (size_t)64 * PD);
        }

#pragma unroll
        for (int kk = 0; kk < BK; kk++) {
            float4 a0 = *(const float4*)&As[s*2048 + kk*128 + ty*8];
            float4 a1 = *(const float4*)&As[s*2048 + kk*128 + ty*8 + 4];
            float4 b0 = *(const float4*)&Bs[s*2048 + kk*128 + tx*8];
            float4 b1 = *(const float4*)&Bs[s*2048 + kk*128 + tx*8 + 4];
            float a[8] = {a0.x, a0.y, a0.z, a0.w, a1.x, a1.y, a1.z, a1.w};
            float b[8] = {b0.x, b0.y, b0.z, b0.w, b1.x, b1.y, b1.z, b1.w};
#pragma unroll
            for (int i = 0; i < 8; i++)
#pragma unroll
                for (int j = 0; j < 8; j++)
                    acc[i][j] = fmaf(a[i], b[j], acc[i][j]);
        }

        if (kt + 1 < NK) {
            const int ns = s ^ 1;
            STS_TILE(ns);
        }
        __syncthreads();
        s ^= 1;
    }
#undef STS_TILE

    // epilogue: scores + per-row keys
    unsigned long long* red = (unsigned long long*)sm;   // [128][16]
    float* crow = scores + (size_t)(bm + ty * 8) * LDSC + (size_t)g * PK + bn + tx * 8;
#pragma unroll
    for (int i = 0; i < 8; i++) {
        float4 v0 = make_float4(acc[i][0], acc[i][1], acc[i][2], acc[i][3]);
        float4 v1 = make_float4(acc[i][4], acc[i][5], acc[i][6], acc[i][7]);
        *(float4*)(crow + (size_t)i * LDSC)     = v0;
        *(float4*)(crow + (size_t)i * LDSC + 4) = v1;
        unsigned long long k = 0;
#pragma unroll
        for (int j = 0; j < 8; j++)
            k = kmax(k, score_key(acc[i][j], bn + tx * 8 + j));
        red[(size_t)(ty * 8 + i) * 16 + tx] = k;
    }
    __syncthreads();
    if (tid < 128) {
        unsigned long long k = 0;
#pragma unroll
        for (int j = 0; j < 16; j++) k = kmax(k, red[(size_t)tid * 16 + j]);
        g_cand[(((size_t)(bm + tid)) * 2 + g) * NTILE + xtile] = k;
    }
}

// ---------------------------------------------------------------------------
// Kernel 1: hybrid dual-pipe GEMM. Class by column tile: x%7>=5 -> FFMA (18),
// else tensor (46). Both classes write scores + argmax candidates.
// ---------------------------------------------------------------------------
__global__ __launch_bounds__(256, 1)
void vq_gemm_hybrid(const float* __restrict__ Z,
                    const float* __restrict__ Wa,
                    const float* __restrict__ Wv,
                    float* __restrict__ scores)
{
    extern __shared__ __align__(16) char sm[];
    const int x   = blockIdx.x;
    const int bm  = blockIdx.y * BM;
    const int g   = blockIdx.z;
    const int tid = threadIdx.x;

    if ((x % 7) >= 5) {
        ffma_path(Z, g ? Wv : Wa, sm, scores, x, bm, g, tid);
    } else {
        tensor_path(sm, scores, x, bm, g, tid);
    }
}

// ---------------------------------------------------------------------------
// Kernel 2: final reduce over 64 tile candidates + gather W[idx].
// ---------------------------------------------------------------------------
__global__ __launch_bounds__(128)
void vq_reduce_gather(const float* __restrict__ Wa,
                      const float* __restrict__ Wv,
                      float* __restrict__ out_st,
                      float* __restrict__ out_q)
{
    const int r = blockIdx.x;
    const int g = blockIdx.y;
    const int tid = threadIdx.x;

    __shared__ unsigned long long s[64];
    __shared__ int s_idx;
    if (tid < 64) s[tid] = g_cand[(((size_t)r) * 2 + g) * NTILE + tid];
    __syncthreads();
    if (tid < 32) {
        unsigned long long k = kmax(s[tid], s[tid + 32]);
#pragma unroll
        for (int off = 16; off > 0; off >>= 1)
            k = kmax(k, __shfl_down_sync(0xFFFFFFFFu, k, off));
        if (tid == 0) s_idx = (int)(~(uint32_t)k);
    }
    __syncthreads();
    const int idx = s_idx;

    const float* __restrict__ Wrow = (g ? Wv : Wa) + (size_t)idx * PD;
    float* st = out_st + (size_t)r * LDZ + (size_t)g * PD;
    float* q  = out_q  + (size_t)r * LDZ + (size_t)g * PD;
    float4 wv = *(const float4*)(Wrow + tid * 4);
    *(float4*)(st + tid * 4) = wv;
    *(float4*)(q  + tid * 4) = wv;
}

// ---------------------------------------------------------------------------
// Harness entry
// ---------------------------------------------------------------------------
extern "C" void kernel_launch(void* const* d_in, const int* in_sizes, int n_in,
                              void* d_out, int out_size)
{
    const float* Z  = (const float*)d_in[0];
    const float* Wa = (const float*)d_in[1];
    const float* Wv = (const float*)d_in[2];

    float* out    = (float*)d_out;
    float* out_st = out;
    float* out_q  = out + (size_t)PB * LDZ;
    float* scores = out + (size_t)2 * PB * LDZ;

    static int smem_set = 0;
    if (!smem_set) {
        cudaFuncSetAttribute(vq_gemm_hybrid, cudaFuncAttributeMaxDynamicSharedMemorySize,
                             SMEM_TOTAL);
        smem_set = 1;
    }

    dim3 sgrid((unsigned)(((size_t)PB * LDZ / 4 + 255) / 256), 3);
    split_kernel<<<sgrid, 256>>>(Z, Wa, Wv);

    dim3 ggrid(NTILE, PB / BM, 2);   // (64, 64, 2)
    vq_gemm_hybrid<<<ggrid, 256, SMEM_TOTAL>>>(Z, Wa, Wv, scores);

    dim3 agrid(PB, 2);
    vq_reduce_gather<<<agrid, 128>>>(Wa, Wv, out_st, out_q);
}

// round 14
// speedup vs baseline: 1.2173x; 1.2173x over previous
#include <cuda_runtime.h>
#include <math_constants.h>
#include <cstdint>

// ---------------- problem constants ----------------
#define PB 8192
#define PK 8192
#define PD 512
#define LDZ 1024
#define LDSC 16384

// ---------------- GEMM tiling (Round-8 proven config) ----------------
#define BM 128
#define BN 128
#define BK 16
#define NK (PD / BK)     // 32
#define NSTG 3
#define NTILE (PK / BN)  // 64

#define ROWB 48
#define T_BYTES (128 * ROWB)           // 6144
#define STG_BYTES (4 * T_BYTES)        // 24576
#define SMEM_TOTAL (NSTG * STG_BYTES)  // 73728
#define OFF_AH 0
#define OFF_AL (T_BYTES)
#define OFF_BH (2 * T_BYTES)
#define OFF_BL (3 * T_BYTES)

// ---------------- device scratch ----------------
__device__ uint16_t g_Zh[(size_t)PB * LDZ];
__device__ uint16_t g_Zl[(size_t)PB * LDZ];
__device__ uint16_t g_Wh[(size_t)2 * PK * PD];
__device__ uint16_t g_Wl[(size_t)2 * PK * PD];
__device__ unsigned long long g_cand[(size_t)PB * 2 * NTILE];   // 8 MB

// ---------------- helpers ----------------
static __device__ __forceinline__ uint32_t pack_bf16(float lo, float hi) {
    uint32_t r;
    asm("cvt.rn.bf16x2.f32 %0, %1, %2;" : "=r"(r) : "f"(hi), "f"(lo));
    return r;
}
static __device__ __forceinline__ void mma16816(float* c, const uint32_t* a, const uint32_t* b) {
    asm volatile(
        "mma.sync.aligned.m16n8k16.row.col.f32.bf16.bf16.f32 "
        "{%0,%1,%2,%3}, {%4,%5,%6,%7}, {%8,%9}, {%0,%1,%2,%3};"
        : "+f"(c[0]), "+f"(c[1]), "+f"(c[2]), "+f"(c[3])
        : "r"(a[0]), "r"(a[1]), "r"(a[2]), "r"(a[3]), "r"(b[0]), "r"(b[1]));
}
static __device__ __forceinline__ uint32_t smem_u32(const void* p) {
    uint32_t a;
    asm("{ .reg .u64 t; cvta.to.shared.u64 t, %1; cvt.u32.u64 %0, t; }" : "=r"(a) : "l"(p));
    return a;
}
static __device__ __forceinline__ uint64_t glob_u64(const void* p) {
    uint64_t a;
    asm("cvta.to.global.u64 %0, %1;" : "=l"(a) : "l"(p));
    return a;
}
// streaming (evict-first) float2 store: scores are write-once, never re-read
static __device__ __forceinline__ void stcs_f2(float* p, float x, float y) {
    asm volatile("st.global.cs.v2.f32 [%0], {%1, %2};" :: "l"(p), "f"(x), "f"(y) : "memory");
}
#define CP16(dst, src) \
    asm volatile("cp.async.cg.shared.global [%0], [%1], 16;" :: "r"(dst), "l"(src))
#define CP_COMMIT() asm volatile("cp.async.commit_group;" ::: "memory")
#define CP_WAIT1()  asm volatile("cp.async.wait_group 1;" ::: "memory")

static __device__ __forceinline__ unsigned long long score_key(float v, int col) {
    uint32_t u = __float_as_uint(v);
    u = (u & 0x80000000u) ? ~u : (u | 0x80000000u);
    return ((unsigned long long)u << 32) | (uint32_t)(~col);
}
static __device__ __forceinline__ unsigned long long kmax(unsigned long long a,
                                                          unsigned long long b) {
    return a > b ? a : b;
}

// ---------------------------------------------------------------------------
// Kernel 0: split f32 -> bf16 hi + bf16 lo residual.
// ---------------------------------------------------------------------------
__global__ __launch_bounds__(256)
void split_kernel(const float* __restrict__ Z,
                  const float* __restrict__ Wa,
                  const float* __restrict__ Wv)
{
    const int region = blockIdx.y;
    const size_t i = ((size_t)blockIdx.x * 256 + threadIdx.x);
    const size_t nquads = (region == 0) ? ((size_t)PB * LDZ / 4) : ((size_t)PK * PD / 4);
    if (i >= nquads) return;

    const float* src;
    uint16_t *dh, *dl;
    if (region == 0)      { src = Z;  dh = g_Zh; dl = g_Zl; }
    else if (region == 1) { src = Wa; dh = g_Wh; dl = g_Wl; }
    else                  { src = Wv; dh = g_Wh + (size_t)PK * PD; dl = g_Wl + (size_t)PK * PD; }

    float4 v = *(const float4*)(src + 4 * i);
    uint32_t h0 = pack_bf16(v.x, v.y);
    uint32_t h1 = pack_bf16(v.z, v.w);
    float r0 = v.x - __uint_as_float(h0 << 16);
    float r1 = v.y - __uint_as_float(h0 & 0xFFFF0000u);
    float r2 = v.z - __uint_as_float(h1 << 16);
    float r3 = v.w - __uint_as_float(h1 & 0xFFFF0000u);
    ((uint2*)dh)[i] = make_uint2(h0, h1);
    ((uint2*)dl)[i] = make_uint2(pack_bf16(r0, r1), pack_bf16(r2, r3));
}

// ---------------------------------------------------------------------------
// Kernel 1: split-bf16 (3-term) mma.sync dual-GEMM — exact Round-8 mainloop
// (BK=16, NSTG=3, scalar LDS frags) + fused argmax epilogue with streaming
// score stores.
// ---------------------------------------------------------------------------
__global__ __launch_bounds__(256, 1)
void vq_gemm_cp(float* __restrict__ scores)
{
    extern __shared__ __align__(16) char sm[];
    const uint32_t sb = smem_u32(sm);

    const int tid  = threadIdx.x;
    const int lane = tid & 31;
    const int w    = tid >> 5;
    const int wm   = w >> 2;
    const int wn   = w & 3;
    const int g    = blockIdx.z;
    const int bm   = blockIdx.y * BM;
    const int bn   = blockIdx.x * BN;

    const int lr = tid >> 1;
    const int kh = tid & 1;
    const uint64_t srcAH = glob_u64(g_Zh + (size_t)(bm + lr) * LDZ + g * PD + kh * 8);
    const uint64_t srcAL = glob_u64(g_Zl + (size_t)(bm + lr) * LDZ + g * PD + kh * 8);
    const uint64_t srcBH = glob_u64(g_Wh + ((size_t)g * PK + bn + lr) * PD + kh * 8);
    const uint64_t srcBL = glob_u64(g_Wl + ((size_t)g * PK + bn + lr) * PD + kh * 8);
    const uint32_t doff = (uint32_t)(lr * ROWB + kh * 16);

    const int qr = lane >> 2;
    const int qi = lane & 3;
    const int qc = qi * 4;

    float acc[4][4][4];
#pragma unroll
    for (int i = 0; i < 4; i++)
#pragma unroll
        for (int j = 0; j < 4; j++)
#pragma unroll
            for (int q = 0; q < 4; q++) acc[i][j][q] = 0.f;

#define ISSUE(slot, kt_) do {                                            \
    const uint32_t st_ = sb + (slot) * STG_BYTES + doff;                 \
    const uint64_t kb_ = (uint64_t)(kt_) * 32;                           \
    CP16(st_ + OFF_AH, srcAH + kb_);                                     \
    CP16(st_ + OFF_AL, srcAL + kb_);                                     \
    CP16(st_ + OFF_BH, srcBH + kb_);                                     \
    CP16(st_ + OFF_BL, srcBL + kb_);                                     \
} while (0)

    ISSUE(0, 0); CP_COMMIT();
    ISSUE(1, 1); CP_COMMIT();

    int sc = 0, si = 2;
    for (int kt = 0; kt < NK; kt++) {
        CP_WAIT1();
        __syncthreads();

        if (kt + 2 < NK) ISSUE(si, kt + 2);
        CP_COMMIT();
        if (++si == NSTG) si = 0;

        const char* stg = sm + sc * STG_BYTES;
        if (++sc == NSTG) sc = 0;

        // ---- fragment loads (LDS.b32, conflict-free via 48B row stride) ----
        uint32_t ah[4][4], al[4][4], bh[4][2], bl[4][2];
#pragma unroll
        for (int mt = 0; mt < 4; mt++) {
            const int m0 = (wm * 64 + mt * 16 + qr) * ROWB + qc;
            const int m8 = m0 + 8 * ROWB;
            ah[mt][0] = *(const uint32_t*)(stg + OFF_AH + m0);
            ah[mt][1] = *(const uint32_t*)(stg + OFF_AH + m8);
            ah[mt][2] = *(const uint32_t*)(stg + OFF_AH + m0 + 16);
            ah[mt][3] = *(const uint32_t*)(stg + OFF_AH + m8 + 16);
            al[mt][0] = *(const uint32_t*)(stg + OFF_AL + m0);
            al[mt][1] = *(const uint32_t*)(stg + OFF_AL + m8);
            al[mt][2] = *(const uint32_t*)(stg + OFF_AL + m0 + 16);
            al[mt][3] = *(const uint32_t*)(stg + OFF_AL + m8 + 16);
        }
#pragma unroll
        for (int nt = 0; nt < 4; nt++) {
            const int n0 = (wn * 32 + nt * 8 + qr) * ROWB + qc;
            bh[nt][0] = *(const uint32_t*)(stg + OFF_BH + n0);
            bh[nt][1] = *(const uint32_t*)(stg + OFF_BH + n0 + 16);
            bl[nt][0] = *(const uint32_t*)(stg + OFF_BL + n0);
            bl[nt][1] = *(const uint32_t*)(stg + OFF_BL + n0 + 16);
        }

        // ---- 3 cross terms; same-acc reuse distance = 16 MMAs ----
#pragma unroll
        for (int nt = 0; nt < 4; nt++)
#pragma unroll
            for (int mt = 0; mt < 4; mt++) mma16816(acc[mt][nt], ah[mt], bh[nt]);
#pragma unroll
        for (int nt = 0; nt < 4; nt++)
#pragma unroll
            for (int mt = 0; mt < 4; mt++) mma16816(acc[mt][nt], al[mt], bh[nt]);
#pragma unroll
        for (int nt = 0; nt < 4; nt++)
#pragma unroll
            for (int mt = 0; mt < 4; mt++) mma16816(acc[mt][nt], ah[mt], bl[nt]);
    }
#undef ISSUE

    // ---- epilogue: streaming score stores + per-row argmax candidate ----
    __syncthreads();                       // mainloop smem dead -> reuse
    unsigned long long* red = (unsigned long long*)sm;   // [128][4]

    const size_t gcol = (size_t)g * PK + bn;
#pragma unroll
    for (int mt = 0; mt < 4; mt++) {
        const int rl0 = wm * 64 + mt * 16 + qr;
        const int r0  = bm + rl0;
        unsigned long long k0 = 0, k1 = 0;
#pragma unroll
        for (int nt = 0; nt < 4; nt++) {
            const int c0 = wn * 32 + nt * 8 + qi * 2;
            stcs_f2(scores + (size_t)r0 * LDSC + gcol + c0,
                    acc[mt][nt][0], acc[mt][nt][1]);
            stcs_f2(scores + (size_t)(r0 + 8) * LDSC + gcol + c0,
                    acc[mt][nt][2], acc[mt][nt][3]);
            const int gc = bn + c0;
            k0 = kmax(k0, kmax(score_key(acc[mt][nt][0], gc), score_key(acc[mt][nt][1], gc + 1)));
            k1 = kmax(k1, kmax(score_key(acc[mt][nt][2], gc), score_key(acc[mt][nt][3], gc + 1)));
        }
#pragma unroll
        for (int m = 1; m <= 2; m <<= 1) {
            k0 = kmax(k0, __shfl_xor_sync(0xFFFFFFFFu, k0, m));
            k1 = kmax(k1, __shfl_xor_sync(0xFFFFFFFFu, k1, m));
        }
        if (qi == 0) {
            red[(size_t)rl0 * 4 + wn]       = k0;
            red[(size_t)(rl0 + 8) * 4 + wn] = k1;
        }
    }
    __syncthreads();
    if (tid < 128) {
        unsigned long long k = kmax(kmax(red[tid * 4 + 0], red[tid * 4 + 1]),
                                    kmax(red[tid * 4 + 2], red[tid * 4 + 3]));
        g_cand[(((size_t)(bm + tid)) * 2 + g) * NTILE + blockIdx.x] = k;
    }
}

// ---------------------------------------------------------------------------
// Kernel 2: final reduce over 64 tile candidates + gather W[idx].
// ---------------------------------------------------------------------------
__global__ __launch_bounds__(128)
void vq_reduce_gather(const float* __restrict__ Wa,
                      const float* __restrict__ Wv,
                      float* __restrict__ out_st,
                      float* __restrict__ out_q)
{
    const int r = blockIdx.x;
    const int g = blockIdx.y;
    const int tid = threadIdx.x;

    __shared__ unsigned long long s[64];
    __shared__ int s_idx;
    if (tid < 64) s[tid] = g_cand[(((size_t)r) * 2 + g) * NTILE + tid];
    __syncthreads();
    if (tid < 32) {
        unsigned long long k = kmax(s[tid], s[tid + 32]);
#pragma unroll
        for (int off = 16; off > 0; off >>= 1)
            k = kmax(k, __shfl_down_sync(0xFFFFFFFFu, k, off));
        if (tid == 0) s_idx = (int)(~(uint32_t)k);
    }
    __syncthreads();
    const int idx = s_idx;

    const float* __restrict__ Wrow = (g ? Wv : Wa) + (size_t)idx * PD;
    float* st = out_st + (size_t)r * LDZ + (size_t)g * PD;
    float* q  = out_q  + (size_t)r * LDZ + (size_t)g * PD;
    float4 wv = *(const float4*)(Wrow + tid * 4);
    *(float4*)(st + tid * 4) = wv;
    *(float4*)(q  + tid * 4) = wv;
}

// ---------------------------------------------------------------------------
// Harness entry
// ---------------------------------------------------------------------------
extern "C" void kernel_launch(void* const* d_in, const int* in_sizes, int n_in,
                              void* d_out, int out_size)
{
    const float* Z  = (const float*)d_in[0];
    const float* Wa = (const float*)d_in[1];
    const float* Wv = (const float*)d_in[2];

    float* out    = (float*)d_out;
    float* out_st = out;
    float* out_q  = out + (size_t)PB * LDZ;
    float* scores = out + (size_t)2 * PB * LDZ;

    static int smem_set = 0;
    if (!smem_set) {
        cudaFuncSetAttribute(vq_gemm_cp, cudaFuncAttributeMaxDynamicSharedMemorySize,
                             SMEM_TOTAL);
        smem_set = 1;
    }

    dim3 sgrid((unsigned)(((size_t)PB * LDZ / 4 + 255) / 256), 3);
    split_kernel<<<sgrid, 256>>>(Z, Wa, Wv);

    dim3 ggrid(NTILE, PB / BM, 2);   // (64, 64, 2)
    vq_gemm_cp<<<ggrid, 256, SMEM_TOTAL>>>(scores);

    dim3 agrid(PB, 2);
    vq_reduce_gather<<<agrid, 128>>>(Wa, Wv, out_st, out_q);
}

// round 15
// speedup vs baseline: 1.2293x; 1.0098x over previous
#include <cuda_runtime.h>
#include <math_constants.h>
#include <cstdint>

// ---------------- problem constants ----------------
#define PB 8192
#define PK 8192
#define PD 512
#define LDZ 1024
#define LDSC 16384

// ---------------- GEMM tiling (Round-8 proven config) ----------------
#define BM 128
#define BN 128
#define BK 16
#define NK (PD / BK)     // 32
#define NSTG 3
#define NTILE (PK / BN)  // 64

#define ROWB 48
#define T_BYTES (128 * ROWB)           // 6144
#define STG_BYTES (4 * T_BYTES)        // 24576
#define SMEM_TOTAL (NSTG * STG_BYTES)  // 73728
#define OFF_AH 0
#define OFF_AL (T_BYTES)
#define OFF_BH (2 * T_BYTES)
#define OFF_BL (3 * T_BYTES)

// ---------------- device scratch ----------------
__device__ uint16_t g_Zh[(size_t)PB * LDZ];
__device__ uint16_t g_Zl[(size_t)PB * LDZ];
__device__ uint16_t g_Wh[(size_t)2 * PK * PD];
__device__ uint16_t g_Wl[(size_t)2 * PK * PD];
__device__ unsigned long long g_cand[(size_t)PB * 2 * NTILE];   // 8 MB

// ---------------- helpers ----------------
static __device__ __forceinline__ uint32_t pack_bf16(float lo, float hi) {
    uint32_t r;
    asm("cvt.rn.bf16x2.f32 %0, %1, %2;" : "=r"(r) : "f"(hi), "f"(lo));
    return r;
}
static __device__ __forceinline__ void mma16816(float* c, const uint32_t* a, const uint32_t* b) {
    asm volatile(
        "mma.sync.aligned.m16n8k16.row.col.f32.bf16.bf16.f32 "
        "{%0,%1,%2,%3}, {%4,%5,%6,%7}, {%8,%9}, {%0,%1,%2,%3};"
        : "+f"(c[0]), "+f"(c[1]), "+f"(c[2]), "+f"(c[3])
        : "r"(a[0]), "r"(a[1]), "r"(a[2]), "r"(a[3]), "r"(b[0]), "r"(b[1]));
}
static __device__ __forceinline__ uint32_t smem_u32(const void* p) {
    uint32_t a;
    asm("{ .reg .u64 t; cvta.to.shared.u64 t, %1; cvt.u32.u64 %0, t; }" : "=r"(a) : "l"(p));
    return a;
}
static __device__ __forceinline__ uint64_t glob_u64(const void* p) {
    uint64_t a;
    asm("cvta.to.global.u64 %0, %1;" : "=l"(a) : "l"(p));
    return a;
}
#define CP16(dst, src) \
    asm volatile("cp.async.cg.shared.global [%0], [%1], 16;" :: "r"(dst), "l"(src))
#define CP_COMMIT() asm volatile("cp.async.commit_group;" ::: "memory")
#define CP_WAIT1()  asm volatile("cp.async.wait_group 1;" ::: "memory")

static __device__ __forceinline__ unsigned long long score_key(float v, int col) {
    uint32_t u = __float_as_uint(v);
    u = (u & 0x80000000u) ? ~u : (u | 0x80000000u);
    return ((unsigned long long)u << 32) | (uint32_t)(~col);
}
static __device__ __forceinline__ unsigned long long kmax(unsigned long long a,
                                                          unsigned long long b) {
    return a > b ? a : b;
}

// ---------------------------------------------------------------------------
// Kernel 0: split f32 -> bf16 hi + bf16 lo residual.
// ---------------------------------------------------------------------------
__global__ __launch_bounds__(256)
void split_kernel(const float* __restrict__ Z,
                  const float* __restrict__ Wa,
                  const float* __restrict__ Wv)
{
    const int region = blockIdx.y;
    const size_t i = ((size_t)blockIdx.x * 256 + threadIdx.x);
    const size_t nquads = (region == 0) ? ((size_t)PB * LDZ / 4) : ((size_t)PK * PD / 4);
    if (i >= nquads) return;

    const float* src;
    uint16_t *dh, *dl;
    if (region == 0)      { src = Z;  dh = g_Zh; dl = g_Zl; }
    else if (region == 1) { src = Wa; dh = g_Wh; dl = g_Wl; }
    else                  { src = Wv; dh = g_Wh + (size_t)PK * PD; dl = g_Wl + (size_t)PK * PD; }

    float4 v = *(const float4*)(src + 4 * i);
    uint32_t h0 = pack_bf16(v.x, v.y);
    uint32_t h1 = pack_bf16(v.z, v.w);
    float r0 = v.x - __uint_as_float(h0 << 16);
    float r1 = v.y - __uint_as_float(h0 & 0xFFFF0000u);
    float r2 = v.z - __uint_as_float(h1 << 16);
    float r3 = v.w - __uint_as_float(h1 & 0xFFFF0000u);
    ((uint2*)dh)[i] = make_uint2(h0, h1);
    ((uint2*)dl)[i] = make_uint2(pack_bf16(r0, r1), pack_bf16(r2, r3));
}

// ---------------------------------------------------------------------------
// Kernel 1: split-bf16 (3-term) mma.sync dual-GEMM — exact Round-8 mainloop
// (BK=16, NSTG=3, scalar LDS frags, plain stores) + slim fused argmax
// epilogue (float compares; one u64 key per row-slot).
// ---------------------------------------------------------------------------
__global__ __launch_bounds__(256, 1)
void vq_gemm_cp(float* __restrict__ scores)
{
    extern __shared__ __align__(16) char sm[];
    const uint32_t sb = smem_u32(sm);

    const int tid  = threadIdx.x;
    const int lane = tid & 31;
    const int w    = tid >> 5;
    const int wm   = w >> 2;
    const int wn   = w & 3;
    const int g    = blockIdx.z;
    const int bm   = blockIdx.y * BM;
    const int bn   = blockIdx.x * BN;

    const int lr = tid >> 1;
    const int kh = tid & 1;
    const uint64_t srcAH = glob_u64(g_Zh + (size_t)(bm + lr) * LDZ + g * PD + kh * 8);
    const uint64_t srcAL = glob_u64(g_Zl + (size_t)(bm + lr) * LDZ + g * PD + kh * 8);
    const uint64_t srcBH = glob_u64(g_Wh + ((size_t)g * PK + bn + lr) * PD + kh * 8);
    const uint64_t srcBL = glob_u64(g_Wl + ((size_t)g * PK + bn + lr) * PD + kh * 8);
    const uint32_t doff = (uint32_t)(lr * ROWB + kh * 16);

    const int qr = lane >> 2;
    const int qi = lane & 3;
    const int qc = qi * 4;

    float acc[4][4][4];
#pragma unroll
    for (int i = 0; i < 4; i++)
#pragma unroll
        for (int j = 0; j < 4; j++)
#pragma unroll
            for (int q = 0; q < 4; q++) acc[i][j][q] = 0.f;

#define ISSUE(slot, kt_) do {                                            \
    const uint32_t st_ = sb + (slot) * STG_BYTES + doff;                 \
    const uint64_t kb_ = (uint64_t)(kt_) * 32;                           \
    CP16(st_ + OFF_AH, srcAH + kb_);                                     \
    CP16(st_ + OFF_AL, srcAL + kb_);                                     \
    CP16(st_ + OFF_BH, srcBH + kb_);                                     \
    CP16(st_ + OFF_BL, srcBL + kb_);                                     \
} while (0)

    ISSUE(0, 0); CP_COMMIT();
    ISSUE(1, 1); CP_COMMIT();

    int sc = 0, si = 2;
    for (int kt = 0; kt < NK; kt++) {
        CP_WAIT1();
        __syncthreads();

        if (kt + 2 < NK) ISSUE(si, kt + 2);
        CP_COMMIT();
        if (++si == NSTG) si = 0;

        const char* stg = sm + sc * STG_BYTES;
        if (++sc == NSTG) sc = 0;

        // ---- fragment loads (LDS.b32, conflict-free via 48B row stride) ----
        uint32_t ah[4][4], al[4][4], bh[4][2], bl[4][2];
#pragma unroll
        for (int mt = 0; mt < 4; mt++) {
            const int m0 = (wm * 64 + mt * 16 + qr) * ROWB + qc;
            const int m8 = m0 + 8 * ROWB;
            ah[mt][0] = *(const uint32_t*)(stg + OFF_AH + m0);
            ah[mt][1] = *(const uint32_t*)(stg + OFF_AH + m8);
            ah[mt][2] = *(const uint32_t*)(stg + OFF_AH + m0 + 16);
            ah[mt][3] = *(const uint32_t*)(stg + OFF_AH + m8 + 16);
            al[mt][0] = *(const uint32_t*)(stg + OFF_AL + m0);
            al[mt][1] = *(const uint32_t*)(stg + OFF_AL + m8);
            al[mt][2] = *(const uint32_t*)(stg + OFF_AL + m0 + 16);
            al[mt][3] = *(const uint32_t*)(stg + OFF_AL + m8 + 16);
        }
#pragma unroll
        for (int nt = 0; nt < 4; nt++) {
            const int n0 = (wn * 32 + nt * 8 + qr) * ROWB + qc;
            bh[nt][0] = *(const uint32_t*)(stg + OFF_BH + n0);
            bh[nt][1] = *(const uint32_t*)(stg + OFF_BH + n0 + 16);
            bl[nt][0] = *(const uint32_t*)(stg + OFF_BL + n0);
            bl[nt][1] = *(const uint32_t*)(stg + OFF_BL + n0 + 16);
        }

        // ---- 3 cross terms; same-acc reuse distance = 16 MMAs ----
#pragma unroll
        for (int nt = 0; nt < 4; nt++)
#pragma unroll
            for (int mt = 0; mt < 4; mt++) mma16816(acc[mt][nt], ah[mt], bh[nt]);
#pragma unroll
        for (int nt = 0; nt < 4; nt++)
#pragma unroll
            for (int mt = 0; mt < 4; mt++) mma16816(acc[mt][nt], al[mt], bh[nt]);
#pragma unroll
        for (int nt = 0; nt < 4; nt++)
#pragma unroll
            for (int mt = 0; mt < 4; mt++) mma16816(acc[mt][nt], ah[mt], bl[nt]);
    }
#undef ISSUE

    // ---- epilogue: plain score stores + slim per-row argmax candidates ----
    __syncthreads();                       // mainloop smem dead -> reuse
    unsigned long long* red = (unsigned long long*)sm;   // [128][4]

    const size_t gcol = (size_t)g * PK + bn;
#pragma unroll
    for (int mt = 0; mt < 4; mt++) {
        const int rl0 = wm * 64 + mt * 16 + qr;
        const int r0  = bm + rl0;
        float bv0 = -CUDART_INF_F, bv1 = -CUDART_INF_F;
        int   bc0 = 0, bc1 = 0;
#pragma unroll
        for (int nt = 0; nt < 4; nt++) {
            const int c0 = wn * 32 + nt * 8 + qi * 2;
            *(float2*)(scores + (size_t)r0 * LDSC + gcol + c0) =
                make_float2(acc[mt][nt][0], acc[mt][nt][1]);
            *(float2*)(scores + (size_t)(r0 + 8) * LDSC + gcol + c0) =
                make_float2(acc[mt][nt][2], acc[mt][nt][3]);
            const int gc = bn + c0;
            // ascending column order within thread -> strict '>' keeps first max
            if (acc[mt][nt][0] > bv0) { bv0 = acc[mt][nt][0]; bc0 = gc; }
            if (acc[mt][nt][1] > bv0) { bv0 = acc[mt][nt][1]; bc0 = gc + 1; }
            if (acc[mt][nt][2] > bv1) { bv1 = acc[mt][nt][2]; bc1 = gc; }
            if (acc[mt][nt][3] > bv1) { bv1 = acc[mt][nt][3]; bc1 = gc + 1; }
        }
        unsigned long long k0 = score_key(bv0, bc0);
        unsigned long long k1 = score_key(bv1, bc1);
        // quad reduce (lanes qi=0..3 hold the same rows); u64 key handles ties
#pragma unroll
        for (int m = 1; m <= 2; m <<= 1) {
            k0 = kmax(k0, __shfl_xor_sync(0xFFFFFFFFu, k0, m));
            k1 = kmax(k1, __shfl_xor_sync(0xFFFFFFFFu, k1, m));
        }
        if (qi == 0) {
            red[(size_t)rl0 * 4 + wn]       = k0;
            red[(size_t)(rl0 + 8) * 4 + wn] = k1;
        }
    }
    __syncthreads();
    if (tid < 128) {
        unsigned long long k = kmax(kmax(red[tid * 4 + 0], red[tid * 4 + 1]),
                                    kmax(red[tid * 4 + 2], red[tid * 4 + 3]));
        g_cand[(((size_t)(bm + tid)) * 2 + g) * NTILE + blockIdx.x] = k;
    }
}

// ---------------------------------------------------------------------------
// Kernel 2: final reduce over 64 tile candidates + gather W[idx].
// ---------------------------------------------------------------------------
__global__ __launch_bounds__(128)
void vq_reduce_gather(const float* __restrict__ Wa,
                      const float* __restrict__ Wv,
                      float* __restrict__ out_st,
                      float* __restrict__ out_q)
{
    const int r = blockIdx.x;
    const int g = blockIdx.y;
    const int tid = threadIdx.x;

    __shared__ unsigned long long s[64];
    __shared__ int s_idx;
    if (tid < 64) s[tid] = g_cand[(((size_t)r) * 2 + g) * NTILE + tid];
    __syncthreads();
    if (tid < 32) {
        unsigned long long k = kmax(s[tid], s[tid + 32]);
#pragma unroll
        for (int off = 16; off > 0; off >>= 1)
            k = kmax(k, __shfl_down_sync(0xFFFFFFFFu, k, off));
        if (tid == 0) s_idx = (int)(~(uint32_t)k);
    }
    __syncthreads();
    const int idx = s_idx;

    const float* __restrict__ Wrow = (g ? Wv : Wa) + (size_t)idx * PD;
    float* st = out_st + (size_t)r * LDZ + (size_t)g * PD;
    float* q  = out_q  + (size_t)r * LDZ + (size_t)g * PD;
    float4 wv = *(const float4*)(Wrow + tid * 4);
    *(float4*)(st + tid * 4) = wv;
    *(float4*)(q  + tid * 4) = wv;
}

// ---------------------------------------------------------------------------
// Harness entry
// ---------------------------------------------------------------------------
extern "C" void kernel_launch(void* const* d_in, const int* in_sizes, int n_in,
                              void* d_out, int out_size)
{
    const float* Z  = (const float*)d_in[0];
    const float* Wa = (const float*)d_in[1];
    const float* Wv = (const float*)d_in[2];

    float* out    = (float*)d_out;
    float* out_st = out;
    float* out_q  = out + (size_t)PB * LDZ;
    float* scores = out + (size_t)2 * PB * LDZ;

    static int smem_set = 0;
    if (!smem_set) {
        cudaFuncSetAttribute(vq_gemm_cp, cudaFuncAttributeMaxDynamicSharedMemorySize,
                             SMEM_TOTAL);
        smem_set = 1;
    }

    dim3 sgrid((unsigned)(((size_t)PB * LDZ / 4 + 255) / 256), 3);
    split_kernel<<<sgrid, 256>>>(Z, Wa, Wv);

    dim3 ggrid(NTILE, PB / BM, 2);   // (64, 64, 2)
    vq_gemm_cp<<<ggrid, 256, SMEM_TOTAL>>>(scores);

    dim3 agrid(PB, 2);
    vq_reduce_gather<<<agrid, 128>>>(Wa, Wv, out_st, out_q);
}

// round 17
// speedup vs baseline: 1.7387x; 1.4144x over previous
#include <cuda_runtime.h>
#include <cuda_fp16.h>
#include <math_constants.h>
#include <cstdint>

// ---------------- problem constants ----------------
#define PB 8192
#define PK 8192
#define PD 512
#define LDZ 1024
#define LDSC 16384

// ---------------- GEMM tiling (R12/R16 carrier) ----------------
#define BM 128
#define BN 128
#define BK 16
#define NK (PD / BK)     // 32
#define NSTG 4
#define NTILE (PK / BN)  // 64

// smem: fp16 tiles [row][k], 32B payload padded to 48B (12-word stride ->
// perfect 32-bank permutation for the 8x4 fragment access pattern)
#define ROWB 48
#define T_BYTES (128 * ROWB)           // 6144
#define STG_BYTES (3 * T_BYTES)        // AH, AL, B = 18432
#define SMEM_TOTAL (NSTG * STG_BYTES)  // 73728
#define OFF_AH 0
#define OFF_AL (T_BYTES)
#define OFF_B  (2 * T_BYTES)

// operand pre-scaling: Z/16, W*16 (product invariant; keeps fp16 W normal)
#define ZSCALE 0.0625f
#define WSCALE 16.0f

// argmax rescue: candidates within EPS of the cheap row max get exact fp32
// recompute. Cheap-score noise sigma ~ 4.4e-7 -> EPS = 2e-5 is ~45 sigma.
#define EPS 2e-5f
#define MAXCAND 32

// ---------------- device scratch ----------------
__device__ uint16_t g_Zh[(size_t)PB * LDZ];
__device__ uint16_t g_Zl[(size_t)PB * LDZ];
__device__ uint16_t g_Wh[(size_t)2 * PK * PD];

// ---------------- helpers ----------------
static __device__ __forceinline__ uint32_t packh(float a, float b) {
    __half2 h = __floats2half2_rn(a, b);   // low = a, high = b
    return *reinterpret_cast<uint32_t*>(&h);
}
static __device__ __forceinline__ void mma16816h(float* c, const uint32_t* a, const uint32_t* b) {
    asm volatile(
        "mma.sync.aligned.m16n8k16.row.col.f32.f16.f16.f32 "
        "{%0,%1,%2,%3}, {%4,%5,%6,%7}, {%8,%9}, {%0,%1,%2,%3};"
        : "+f"(c[0]), "+f"(c[1]), "+f"(c[2]), "+f"(c[3])
        : "r"(a[0]), "r"(a[1]), "r"(a[2]), "r"(a[3]), "r"(b[0]), "r"(b[1]));
}
static __device__ __forceinline__ uint32_t smem_u32(const void* p) {
    uint32_t a;
    asm("{ .reg .u64 t; cvta.to.shared.u64 t, %1; cvt.u32.u64 %0, t; }" : "=r"(a) : "l"(p));
    return a;
}
static __device__ __forceinline__ uint64_t glob_u64(const void* p) {
    uint64_t a;
    asm("cvta.to.global.u64 %0, %1;" : "=l"(a) : "l"(p));
    return a;
}
#define CP16(dst, src) \
    asm volatile("cp.async.cg.shared.global [%0], [%1], 16;" :: "r"(dst), "l"(src))
#define CP_COMMIT() asm volatile("cp.async.commit_group;" ::: "memory")
#define CP_WAIT1()  asm volatile("cp.async.wait_group 1;" ::: "memory")
#define CP_WAIT2()  asm volatile("cp.async.wait_group 2;" ::: "memory")

static __device__ __forceinline__ unsigned long long score_key(float v, int col) {
    uint32_t u = __float_as_uint(v);
    u = (u & 0x80000000u) ? ~u : (u | 0x80000000u);
    return ((unsigned long long)u << 32) | (uint32_t)(~col);
}

// per-warp fragment set (double-buffered in the mainloop)
struct Frags {
    uint32_t ah[4][4], al[4][4], b[4][2];
};

// ---------------------------------------------------------------------------
// Kernel 0: region 0: Z/16 -> fp16 hi + fp16 lo residual.
//           regions 1,2: 16*W -> single fp16.
// ---------------------------------------------------------------------------
__global__ __launch_bounds__(256)
void split_kernel(const float* __restrict__ Z,
                  const float* __restrict__ Wa,
                  const float* __restrict__ Wv)
{
    const int region = blockIdx.y;
    const size_t i = ((size_t)blockIdx.x * 256 + threadIdx.x);
    const size_t nquads = (region == 0) ? ((size_t)PB * LDZ / 4) : ((size_t)PK * PD / 4);
    if (i >= nquads) return;

    if (region == 0) {
        float4 v = *(const float4*)(Z + 4 * i);
        float x0 = v.x * ZSCALE, x1 = v.y * ZSCALE, x2 = v.z * ZSCALE, x3 = v.w * ZSCALE;
        __half h0 = __float2half_rn(x0), h1 = __float2half_rn(x1);
        __half h2 = __float2half_rn(x2), h3 = __float2half_rn(x3);
        float l0 = x0 - __half2float(h0), l1 = x1 - __half2float(h1);
        float l2 = x2 - __half2float(h2), l3 = x3 - __half2float(h3);
        ((uint2*)g_Zh)[i] = make_uint2(packh(__half2float(h0), __half2float(h1)),
                                       packh(__half2float(h2), __half2float(h3)));
        ((uint2*)g_Zl)[i] = make_uint2(packh(l0, l1), packh(l2, l3));
    } else {
        const float* src = (region == 1) ? Wa : Wv;
        uint16_t* dh = g_Wh + (region == 2 ? (size_t)PK * PD : 0);
        float4 v = *(const float4*)(src + 4 * i);
        ((uint2*)dh)[i] = make_uint2(packh(v.x * WSCALE, v.y * WSCALE),
                                     packh(v.z * WSCALE, v.w * WSCALE));
    }
}

// ---------------------------------------------------------------------------
// Kernel 1: fp16 2-term mma.sync dual-GEMM (NSTG=4, frag double-buffer),
// plain score stores (no fused argmax — rescue kernel owns argmax).
// ---------------------------------------------------------------------------
__global__ __launch_bounds__(256, 1)
void vq_gemm_cp(float* __restrict__ scores)
{
    extern __shared__ __align__(16) char sm[];
    const uint32_t sb = smem_u32(sm);

    const int tid  = threadIdx.x;
    const int lane = tid & 31;
    const int w    = tid >> 5;
    const int wm   = w >> 2;
    const int wn   = w & 3;
    const int g    = blockIdx.z;
    const int bm   = blockIdx.y * BM;
    const int bn   = blockIdx.x * BN;

    const int lr = tid >> 1;
    const int kh = tid & 1;
    const uint64_t srcAH = glob_u64(g_Zh + (size_t)(bm + lr) * LDZ + g * PD + kh * 8);
    const uint64_t srcAL = glob_u64(g_Zl + (size_t)(bm + lr) * LDZ + g * PD + kh * 8);
    const uint64_t srcB  = glob_u64(g_Wh + ((size_t)g * PK + bn + lr) * PD + kh * 8);
    const uint32_t doff = (uint32_t)(lr * ROWB + kh * 16);

    const int qr = lane >> 2;
    const int qi = lane & 3;
    const int qc = qi * 4;
    const int a_base = (wm * 64 + qr) * ROWB + qc;
    const int b_base = (wn * 32 + qr) * ROWB + qc;

    float acc[4][4][4];
#pragma unroll
    for (int i = 0; i < 4; i++)
#pragma unroll
        for (int j = 0; j < 4; j++)
#pragma unroll
            for (int q = 0; q < 4; q++) acc[i][j][q] = 0.f;

#define ISSUE(slot, kt_) do {                                            \
    const uint32_t st_ = sb + (slot) * STG_BYTES + doff;                 \
    const uint64_t kb_ = (uint64_t)(kt_) * 32;                           \
    CP16(st_ + OFF_AH, srcAH + kb_);                                     \
    CP16(st_ + OFF_AL, srcAL + kb_);                                     \
    CP16(st_ + OFF_B,  srcB  + kb_);                                     \
} while (0)

#define LOAD_FRAGS(F, stg) do {                                                   \
    _Pragma("unroll")                                                             \
    for (int mt = 0; mt < 4; mt++) {                                              \
        const int m0 = a_base + mt * 16 * ROWB;                                   \
        const int m8 = m0 + 8 * ROWB;                                             \
        (F).ah[mt][0] = *(const uint32_t*)((stg) + OFF_AH + m0);                  \
        (F).ah[mt][1] = *(const uint32_t*)((stg) + OFF_AH + m8);                  \
        (F).ah[mt][2] = *(const uint32_t*)((stg) + OFF_AH + m0 + 16);             \
        (F).ah[mt][3] = *(const uint32_t*)((stg) + OFF_AH + m8 + 16);             \
        (F).al[mt][0] = *(const uint32_t*)((stg) + OFF_AL + m0);                  \
        (F).al[mt][1] = *(const uint32_t*)((stg) + OFF_AL + m8);                  \
        (F).al[mt][2] = *(const uint32_t*)((stg) + OFF_AL + m0 + 16);             \
        (F).al[mt][3] = *(const uint32_t*)((stg) + OFF_AL + m8 + 16);             \
    }                                                                             \
    _Pragma("unroll")                                                             \
    for (int nt = 0; nt < 4; nt++) {                                              \
        const int n0 = b_base + nt * 8 * ROWB;                                    \
        (F).b[nt][0] = *(const uint32_t*)((stg) + OFF_B + n0);                    \
        (F).b[nt][1] = *(const uint32_t*)((stg) + OFF_B + n0 + 16);               \
    }                                                                             \
} while (0)

#define MMA_ALL(F) do {                                                           \
    _Pragma("unroll")                                                             \
    for (int nt = 0; nt < 4; nt++)                                                \
        _Pragma("unroll")                                                         \
        for (int mt = 0; mt < 4; mt++) mma16816h(acc[mt][nt], (F).ah[mt], (F).b[nt]); \
    _Pragma("unroll")                                                             \
    for (int nt = 0; nt < 4; nt++)                                                \
        _Pragma("unroll")                                                         \
        for (int mt = 0; mt < 4; mt++) mma16816h(acc[mt][nt], (F).al[mt], (F).b[nt]); \
} while (0)

    ISSUE(0, 0); CP_COMMIT();
    ISSUE(1, 1); CP_COMMIT();
    ISSUE(2, 2); CP_COMMIT();

    Frags F0, F1;
    CP_WAIT2();
    __syncthreads();
    LOAD_FRAGS(F0, sm);

#pragma unroll 2
    for (int kt = 0; kt < NK; kt++) {
        CP_WAIT1();
        __syncthreads();

        if (kt + 3 < NK) ISSUE((kt + 3) & 3, kt + 3);
        CP_COMMIT();

        if (kt & 1) {
            if (kt + 1 < NK) LOAD_FRAGS(F0, sm + ((kt + 1) & 3) * STG_BYTES);
            MMA_ALL(F1);
        } else {
            if (kt + 1 < NK) LOAD_FRAGS(F1, sm + ((kt + 1) & 3) * STG_BYTES);
            MMA_ALL(F0);
        }
    }
#undef ISSUE
#undef LOAD_FRAGS
#undef MMA_ALL

    // ---- epilogue: plain score stores ----
    const size_t gcol = (size_t)g * PK + bn;
#pragma unroll
    for (int mt = 0; mt < 4; mt++) {
        const int r0 = bm + wm * 64 + mt * 16 + qr;
#pragma unroll
        for (int nt = 0; nt < 4; nt++) {
            const int c0 = wn * 32 + nt * 8 + qi * 2;
            *(float2*)(scores + (size_t)r0 * LDSC + gcol + c0) =
                make_float2(acc[mt][nt][0], acc[mt][nt][1]);
            *(float2*)(scores + (size_t)(r0 + 8) * LDSC + gcol + c0) =
                make_float2(acc[mt][nt][2], acc[mt][nt][3]);
        }
    }
}

// ---------------------------------------------------------------------------
// Kernel 2: argmax with exact rescue + gather.
// Cheap scores pick the winner unless other columns sit within EPS of the
// max; those ties are recomputed exactly in fp32 from the original inputs.
// ---------------------------------------------------------------------------
__global__ __launch_bounds__(256)
void vq_argmax_rescue(const float* __restrict__ scores,
                      const float* __restrict__ Z,
                      const float* __restrict__ Wa,
                      const float* __restrict__ Wv,
                      float* __restrict__ out_st,
                      float* __restrict__ out_q)
{
    const int r = blockIdx.x;
    const int g = blockIdx.y;
    const int tid = threadIdx.x;
    const int lane = tid & 31;
    const int wid = tid >> 5;

    __shared__ float sr[PK];              // 32 KB row cache
    __shared__ float sv[256];
    __shared__ int   s_cnt;
    __shared__ int   s_cand[MAXCAND];
    __shared__ unsigned long long s_best;

    const float* __restrict__ srow = scores + (size_t)r * LDSC + (size_t)g * PK;

    // load row to smem (float4) + per-thread max
    float best = -CUDART_INF_F;
#pragma unroll
    for (int it = 0; it < PK / (256 * 4); it++) {
        const int k4 = (it * 256 + tid) * 4;
        float4 v = *(const float4*)(srow + k4);
        *(float4*)(sr + k4) = v;
        best = fmaxf(best, fmaxf(fmaxf(v.x, v.y), fmaxf(v.z, v.w)));
    }
    sv[tid] = best;
    if (tid == 0) { s_cnt = 0; s_best = 0ULL; }
    __syncthreads();

    // block max (value only)
#pragma unroll
    for (int stride = 128; stride > 0; stride >>= 1) {
        if (tid < stride) sv[tid] = fmaxf(sv[tid], sv[tid + stride]);
        __syncthreads();
    }
    const float rowmax = sv[0];

    // collect candidates within EPS of max
    const float thresh = rowmax - EPS;
    for (int k = tid; k < PK; k += 256) {
        if (sr[k] >= thresh) {
            int i = atomicAdd(&s_cnt, 1);
            if (i < MAXCAND) s_cand[i] = k;
        }
    }
    __syncthreads();
    const int ncand = (s_cnt < MAXCAND) ? s_cnt : MAXCAND;

    // exact fp32 recompute for candidates (one warp per candidate)
    const float* __restrict__ zrow = Z + (size_t)r * LDZ + (size_t)g * PD;
    const float* __restrict__ Wb   = g ? Wv : Wa;
    for (int j = wid; j < ncand; j += 8) {
        const int col = s_cand[j];
        const float* __restrict__ wrow = Wb + (size_t)col * PD;
        float s = 0.f;
#pragma unroll
        for (int t = 0; t < PD / 32; t++)
            s = fmaf(zrow[t * 32 + lane], wrow[t * 32 + lane], s);
#pragma unroll
        for (int off = 16; off > 0; off >>= 1)
            s += __shfl_xor_sync(0xFFFFFFFFu, s, off);
        if (lane == 0)
            atomicMax(&s_best, score_key(s, col));
    }
    __syncthreads();
    const int idx = (int)(~(uint32_t)s_best);

    // gather
    const float* __restrict__ Wrow = Wb + (size_t)idx * PD;
    float* st = out_st + (size_t)r * LDZ + (size_t)g * PD;
    float* q  = out_q  + (size_t)r * LDZ + (size_t)g * PD;
    if (tid < 128) {
        float4 wv = *(const float4*)(Wrow + tid * 4);
        *(float4*)(st + tid * 4) = wv;
        *(float4*)(q  + tid * 4) = wv;
    }
}

// ---------------------------------------------------------------------------
// Harness entry
// ---------------------------------------------------------------------------
extern "C" void kernel_launch(void* const* d_in, const int* in_sizes, int n_in,
                              void* d_out, int out_size)
{
    const float* Z  = (const float*)d_in[0];
    const float* Wa = (const float*)d_in[1];
    const float* Wv = (const float*)d_in[2];

    float* out    = (float*)d_out;
    float* out_st = out;
    float* out_q  = out + (size_t)PB * LDZ;
    float* scores = out + (size_t)2 * PB * LDZ;

    static int smem_set = 0;
    if (!smem_set) {
        cudaFuncSetAttribute(vq_gemm_cp, cudaFuncAttributeMaxDynamicSharedMemorySize,
                             SMEM_TOTAL);
        smem_set = 1;
    }

    dim3 sgrid((unsigned)(((size_t)PB * LDZ / 4 + 255) / 256), 3);
    split_kernel<<<sgrid, 256>>>(Z, Wa, Wv);

    dim3 ggrid(NTILE, PB / BM, 2);   // (64, 64, 2)
    vq_gemm_cp<<<ggrid, 256, SMEM_TOTAL>>>(scores);

    dim3 agrid(PB, 2);
    vq_argmax_rescue<<<agrid, 256>>>(scores, Z, Wa, Wv, out_st, out_q);
}